// round 2
// baseline (speedup 1.0000x reference)
#include <cuda_runtime.h>
#include <math.h>

// Problem constants
#define B_  2
#define LQ_ 2048
#define LK_ 2048
#define D_  128
#define F_  128
#define H_  8

// Tiling
#define BQ  64     // query rows per block
#define BKT 64     // key rows per tile
#define PSTR 65    // padded stride for P (softmax probs) smem tile

// smem floats: Qs[128][64] + Ks[128][64] + Vs[64][128] + Ps[64][65]
#define SMEM_FLOATS (D_*BQ + D_*BKT + BKT*F_ + BKT*PSTR)

// Scratch (device globals: no runtime allocation allowed)
__device__ float g_s[H_*D_];                       // per-head fused diag scale (incl 1/sqrt(D))
__device__ float O2_s[H_*F_*F_];                   // dv-folded output projection [H*F, F]
__device__ float Oh_s[(size_t)B_*H_*LQ_*F_];       // raw attention output [B,H,Lq,F] (16 MB)

// ---------------------------------------------------------------------------
// Prep: g[h,d] = WQ[h,d,d]*WK[h,d,d]/sqrt(D);  O2[h*F+f, fo] = WV[h,f,f]*O[h*F+f, fo]
// ---------------------------------------------------------------------------
__global__ void prep_kernel(const float* __restrict__ WQ, const float* __restrict__ WK,
                            const float* __restrict__ WV, const float* __restrict__ O) {
    int idx = blockIdx.x * blockDim.x + threadIdx.x;
    if (idx < H_*D_) {
        int h = idx / D_, d = idx % D_;
        float dq = WQ[(h*D_ + d)*D_ + d];
        float dk = WK[(h*D_ + d)*D_ + d];
        g_s[idx] = dq * dk * rsqrtf((float)D_);
    }
    if (idx < H_*F_*F_) {
        int hf = idx / F_;
        int h = hf / F_, f = hf % F_;
        float dv = WV[(h*F_ + f)*F_ + f];
        O2_s[idx] = dv * O[idx];
    }
}

// ---------------------------------------------------------------------------
// Flash attention (fp32): one block = (q-tile of 64, head, batch).
// Thread grid 16x16: GEMM1 each thread 4x4 of S; GEMM2 each thread 4 rows x 8 cols.
// Qs/Ks stored d-major [d][64] so frag loads are conflict-free LDS.128.
// ---------------------------------------------------------------------------
__global__ __launch_bounds__(256)
void attn_kernel(const float* __restrict__ XQ, const float* __restrict__ XK,
                 const float* __restrict__ XV, const int* __restrict__ MASK) {
    extern __shared__ float sm[];
    float* Qs = sm;                 // [128][64]
    float* Ks = Qs + D_*BQ;         // [128][64]
    float* Vs = Ks + D_*BKT;        // [64][128]
    float* Ps = Vs + BKT*F_;        // [64][65]  Ps[j][i] (transposed probs)

    const int tid = threadIdx.x;
    const int tx  = tid & 15;       // col group
    const int ty  = tid >> 4;       // row group
    const int q0  = blockIdx.x * BQ;
    const int h   = blockIdx.y;
    const int b   = blockIdx.z;

    const float* gq = g_s + h * D_;

    // ---- Load Q tile transposed + scaled: Qs[d][i] = XQ[b, q0+i, d] * g[h,d] ----
    // lanes differ in i -> STS conflict-free; global 16B @ 512B stride (L2-fed, once per block)
    #pragma unroll
    for (int it = 0; it < 8; ++it) {
        int u  = it*256 + tid;
        int i  = u & 63;
        int d  = (u >> 6) * 4;
        const float4 q = *(const float4*)(XQ + ((size_t)(b*LQ_ + q0 + i))*D_ + d);
        Qs[(d+0)*64 + i] = q.x * gq[d+0];
        Qs[(d+1)*64 + i] = q.y * gq[d+1];
        Qs[(d+2)*64 + i] = q.z * gq[d+2];
        Qs[(d+3)*64 + i] = q.w * gq[d+3];
    }

    float m_prev[4], l_acc[4], Oacc[4][8];
    #pragma unroll
    for (int r = 0; r < 4; ++r) {
        m_prev[r] = -1e30f;
        l_acc[r]  = 0.0f;
        #pragma unroll
        for (int c = 0; c < 8; ++c) Oacc[r][c] = 0.0f;
    }

    for (int kt = 0; kt < LK_/BKT; ++kt) {
        const int k0 = kt * BKT;
        __syncthreads();   // previous GEMM2 done reading Vs/Ps

        // ---- Load K tile transposed: Ks[d][j] = XK[b, k0+j, d] ----
        #pragma unroll
        for (int it = 0; it < 8; ++it) {
            int u  = it*256 + tid;
            int j  = u & 63;
            int d  = (u >> 6) * 4;
            const float4 kv = *(const float4*)(XK + ((size_t)(b*LK_ + k0 + j))*D_ + d);
            Ks[(d+0)*64 + j] = kv.x;
            Ks[(d+1)*64 + j] = kv.y;
            Ks[(d+2)*64 + j] = kv.z;
            Ks[(d+3)*64 + j] = kv.w;
        }
        // ---- Load V tile row-major (coalesced, conflict-free STS.128) ----
        #pragma unroll
        for (int it = 0; it < 8; ++it) {
            int u   = it*256 + tid;
            int f4  = (u & 31) * 4;
            int krw = u >> 5;
            *(float4*)(Vs + krw*F_ + f4) =
                *(const float4*)(XV + ((size_t)(b*LK_ + k0 + krw))*F_ + f4);
        }
        __syncthreads();

        // ---- GEMM1: S[4][4] = Qtile @ Ktile^T ----
        float S[4][4];
        #pragma unroll
        for (int r = 0; r < 4; ++r)
            #pragma unroll
            for (int c = 0; c < 4; ++c) S[r][c] = 0.0f;

        const float* Qp = Qs + 4*ty;
        const float* Kp = Ks + 4*tx;
        #pragma unroll 16
        for (int d = 0; d < D_; ++d) {
            const float4 qv = *(const float4*)(Qp + d*64);
            const float4 kv = *(const float4*)(Kp + d*64);
            const float qa[4] = {qv.x, qv.y, qv.z, qv.w};
            const float ka[4] = {kv.x, kv.y, kv.z, kv.w};
            #pragma unroll
            for (int r = 0; r < 4; ++r)
                #pragma unroll
                for (int c = 0; c < 4; ++c) S[r][c] = fmaf(qa[r], ka[c], S[r][c]);
        }

        // ---- Mask (int4 coalesced loads) ----
        #pragma unroll
        for (int r = 0; r < 4; ++r) {
            const int4 mr = *(const int4*)(MASK +
                ((size_t)(b*LQ_ + q0 + 4*ty + r))*LK_ + k0 + 4*tx);
            if (mr.x == 0) S[r][0] = -1e30f;
            if (mr.y == 0) S[r][1] = -1e30f;
            if (mr.z == 0) S[r][2] = -1e30f;
            if (mr.w == 0) S[r][3] = -1e30f;
        }

        // ---- Online softmax (row reductions across the 16 tx lanes) ----
        float corr[4];
        #pragma unroll
        for (int r = 0; r < 4; ++r) {
            float tmax = fmaxf(fmaxf(S[r][0], S[r][1]), fmaxf(S[r][2], S[r][3]));
            #pragma unroll
            for (int off = 1; off < 16; off <<= 1)
                tmax = fmaxf(tmax, __shfl_xor_sync(0xffffffffu, tmax, off, 16));
            const float mnew = fmaxf(m_prev[r], tmax);
            corr[r] = __expf(m_prev[r] - mnew);
            m_prev[r] = mnew;
            float ps = 0.0f;
            #pragma unroll
            for (int c = 0; c < 4; ++c) {
                const float p = __expf(S[r][c] - mnew);
                ps += p;
                Ps[(4*tx + c)*PSTR + 4*ty + r] = p;   // transposed store
            }
            #pragma unroll
            for (int off = 1; off < 16; off <<= 1)
                ps += __shfl_xor_sync(0xffffffffu, ps, off, 16);
            l_acc[r] = l_acc[r]*corr[r] + ps;
        }
        __syncthreads();

        // ---- Rescale accumulators, GEMM2: Oacc += P @ V ----
        #pragma unroll
        for (int r = 0; r < 4; ++r)
            #pragma unroll
            for (int c = 0; c < 8; ++c) Oacc[r][c] *= corr[r];

        const float* Vp = Vs + 8*tx;
        const float* Pp = Ps + 4*ty;
        #pragma unroll 8
        for (int k = 0; k < BKT; ++k) {
            const float4 v0 = *(const float4*)(Vp + k*F_);
            const float4 v1 = *(const float4*)(Vp + k*F_ + 4);
            const float va[8] = {v0.x, v0.y, v0.z, v0.w, v1.x, v1.y, v1.z, v1.w};
            #pragma unroll
            for (int r = 0; r < 4; ++r) {
                const float p = Pp[k*PSTR + r];
                #pragma unroll
                for (int c = 0; c < 8; ++c) Oacc[r][c] = fmaf(p, va[c], Oacc[r][c]);
            }
        }
    }

    // ---- Epilogue: normalize, write raw head output to scratch ----
    #pragma unroll
    for (int r = 0; r < 4; ++r) {
        const float inv = 1.0f / l_acc[r];
        float4 o0, o1;
        o0.x = Oacc[r][0]*inv; o0.y = Oacc[r][1]*inv;
        o0.z = Oacc[r][2]*inv; o0.w = Oacc[r][3]*inv;
        o1.x = Oacc[r][4]*inv; o1.y = Oacc[r][5]*inv;
        o1.z = Oacc[r][6]*inv; o1.w = Oacc[r][7]*inv;
        const size_t base = ((size_t)((b*H_ + h)*LQ_) + q0 + 4*ty + r)*F_ + 8*tx;
        *(float4*)(Oh_s + base)     = o0;
        *(float4*)(Oh_s + base + 4) = o1;
    }
}

// ---------------------------------------------------------------------------
// Projection: Y[(b,q), fo] = sum_{h,f} Oh[b,h,q,f] * O2[h*F+f, fo]
// GEMM [4096 x 128] = [4096 x 1024] @ [1024 x 128]. BM=32, BK=64.
// ---------------------------------------------------------------------------
__global__ __launch_bounds__(256, 2)
void proj_kernel(float* __restrict__ Y) {
    __shared__ float As[64*32];     // [k][row]
    __shared__ float Bs[64*F_];     // [k][fo]

    const int tid = threadIdx.x;
    const int tx  = tid & 15;
    const int ty  = tid >> 4;
    const int row0 = blockIdx.x * 32;

    float acc[2][8];
    #pragma unroll
    for (int r = 0; r < 2; ++r)
        #pragma unroll
        for (int c = 0; c < 8; ++c) acc[r][c] = 0.0f;

    for (int k0 = 0; k0 < H_*F_; k0 += 64) {
        __syncthreads();
        // Load A tile transposed: As[k][row]
        #pragma unroll
        for (int it = 0; it < 2; ++it) {
            int u  = it*256 + tid;
            int rr = u & 31;
            int k  = k0 + (u >> 5) * 4;
            int row = row0 + rr;
            int bb = row >> 11;            // / 2048
            int q  = row & 2047;
            int hh = k >> 7;               // / 128
            int f  = k & 127;
            const float4 a = *(const float4*)(Oh_s +
                ((size_t)((bb*H_ + hh)*LQ_) + q)*F_ + f);
            int kl = k - k0;
            As[(kl+0)*32 + rr] = a.x;
            As[(kl+1)*32 + rr] = a.y;
            As[(kl+2)*32 + rr] = a.z;
            As[(kl+3)*32 + rr] = a.w;
        }
        // Load B tile (coalesced)
        #pragma unroll
        for (int it = 0; it < 8; ++it) {
            int u  = it*256 + tid;
            int f4 = (u & 31) * 4;
            int kk = u >> 5;
            *(float4*)(Bs + kk*F_ + f4) =
                *(const float4*)(O2_s + (size_t)(k0 + kk)*F_ + f4);
        }
        __syncthreads();

        #pragma unroll 8
        for (int kk = 0; kk < 64; ++kk) {
            const float a0 = As[kk*32 + 2*ty];
            const float a1 = As[kk*32 + 2*ty + 1];
            const float4 b0 = *(const float4*)(Bs + kk*F_ + 8*tx);
            const float4 b1 = *(const float4*)(Bs + kk*F_ + 8*tx + 4);
            const float ba[8] = {b0.x, b0.y, b0.z, b0.w, b1.x, b1.y, b1.z, b1.w};
            #pragma unroll
            for (int c = 0; c < 8; ++c) {
                acc[0][c] = fmaf(a0, ba[c], acc[0][c]);
                acc[1][c] = fmaf(a1, ba[c], acc[1][c]);
            }
        }
    }

    #pragma unroll
    for (int r = 0; r < 2; ++r) {
        const int row = row0 + 2*ty + r;
        float4 y0, y1;
        y0.x = acc[r][0]; y0.y = acc[r][1]; y0.z = acc[r][2]; y0.w = acc[r][3];
        y1.x = acc[r][4]; y1.y = acc[r][5]; y1.z = acc[r][6]; y1.w = acc[r][7];
        *(float4*)(Y + (size_t)row*F_ + 8*tx)     = y0;
        *(float4*)(Y + (size_t)row*F_ + 8*tx + 4) = y1;
    }
}

// ---------------------------------------------------------------------------
extern "C" void kernel_launch(void* const* d_in, const int* in_sizes, int n_in,
                              void* d_out, int out_size) {
    const float* XQ   = (const float*)d_in[0];
    const float* XK   = (const float*)d_in[1];
    const float* XV   = (const float*)d_in[2];
    const int*   MASK = (const int*)  d_in[3];
    const float* WQ   = (const float*)d_in[4];
    const float* WK   = (const float*)d_in[5];
    const float* WV   = (const float*)d_in[6];
    const float* O    = (const float*)d_in[7];
    float* Y = (float*)d_out;

    cudaFuncSetAttribute(attn_kernel, cudaFuncAttributeMaxDynamicSharedMemorySize,
                         SMEM_FLOATS * (int)sizeof(float));

    prep_kernel<<<(H_*F_*F_ + 255)/256, 256>>>(WQ, WK, WV, O);

    dim3 agrid(LQ_/BQ, H_, B_);
    attn_kernel<<<agrid, 256, SMEM_FLOATS * sizeof(float)>>>(XQ, XK, XV, MASK);

    proj_kernel<<<(B_*LQ_)/32, 256>>>(Y);
}